// round 1
// baseline (speedup 1.0000x reference)
#include <cuda_runtime.h>
#include <cuda_bf16.h>
#include <math.h>

// BlockGCN fused kernel.
// out = relu( BN( sum_k conv_k( einsum(x, BnA_k) ) ) + x )
// Shapes: x (32,128,256,23), K=3, H=8, cin_g=cout_g=16, V=23.

#define NK 3
#define NH 8
#define NV 23
#define NVP 24          // padded V
#define CG 16           // channels per group
#define NT 256
#define NN 32
#define NC 128
#define TB 16           // timesteps per block

// Precomputed small tensors (device globals; no allocation).
__device__ float g_bna[NK][NH][NV][NVP];   // [k][h][w][v] : BnA transposed, v padded with 0
__device__ float g_ws[NK][NH][CG][CG];     // BN-scale folded conv weights [k][h][o][c]
__device__ float g_bias[NC];               // folded bias: inv*sum_k b + beta - mean*inv

__global__ void precompute_kernel(const float* __restrict__ emb,
                                  const float* __restrict__ A,
                                  const float* __restrict__ conv_w,
                                  const float* __restrict__ conv_b,
                                  const float* __restrict__ gamma,
                                  const float* __restrict__ beta,
                                  const float* __restrict__ mean,
                                  const float* __restrict__ var,
                                  const int*   __restrict__ hop,
                                  int n_hop)
{
    int b = blockIdx.x;
    if (b < NK * NH) {
        int k = b / NH, h = b % NH;
        int w = threadIdx.x;
        if (w < NV) {
            float Bc[NV], Ac[NV];
            float sB = 0.f, sA = 0.f;
            #pragma unroll
            for (int v = 0; v < NV; v++) {
                float bb = emb[(k * NH + h) * n_hop + hop[v * NV + w]];
                float aa = A[((k * NH + h) * NV + v) * NV + w];
                Bc[v] = bb; Ac[v] = aa;
                sB += bb * bb; sA += aa * aa;
            }
            float iB = 1.f / (sqrtf(sB) + 1e-4f);
            float iA = 1.f / (sqrtf(sA) + 1e-4f);
            #pragma unroll
            for (int v = 0; v < NV; v++)
                g_bna[k][h][w][v] = Bc[v] * iB + Ac[v] * iA;
            g_bna[k][h][w][NV] = 0.f;   // pad
        }
    } else {
        int tid = threadIdx.x;
        // Folded weights: ws[k][h][o][c] = conv_w[k*128 + h*16 + o][c] * inv[och]
        for (int idx = tid; idx < NK * NC * CG; idx += blockDim.x) {
            int row = idx / CG, c = idx % CG;
            int k = row / NC, och = row % NC;
            float inv = gamma[och] * rsqrtf(var[och] + 1e-5f);
            int h = och / CG, o = och % CG;
            g_ws[k][h][o][c] = conv_w[row * CG + c] * inv;
        }
        // Folded bias
        for (int och = tid; och < NC; och += blockDim.x) {
            float inv = gamma[och] * rsqrtf(var[och] + 1e-5f);
            float sb = conv_b[och] + conv_b[NC + och] + conv_b[2 * NC + och];
            g_bias[och] = sb * inv + beta[och] - mean[och] * inv;
        }
    }
}

__global__ __launch_bounds__(384)
void blockgcn_main_kernel(const float* __restrict__ x, float* __restrict__ out)
{
    __shared__ __align__(16) float xs[CG][TB][NVP];       // x tile, v padded w/ 0
    __shared__ __align__(16) float bna_s[NK][NV][NVP];    // [k][w][v]
    __shared__ __align__(16) float ws_s[NK][CG][CG];      // [k][o][c]
    __shared__ float bias_s[CG];

    const int tile = blockIdx.x;   // 0..15
    const int n    = blockIdx.y;   // 0..31
    const int h    = blockIdx.z;   // 0..7
    const int t0   = tile * TB;
    const int tid  = threadIdx.x;

    // ---- stage x tile: 16 channels x TB x 23 (coalesced-ish) ----
    const float* xbase = x + ((size_t)(n * NC + h * CG)) * (NT * NV) + (size_t)t0 * NV;
    for (int idx = tid; idx < CG * TB * NV; idx += 384) {
        int c = idx / (TB * NV);
        int r = idx % (TB * NV);
        int t = r / NV, v = r % NV;
        xs[c][t][v] = xbase[(size_t)c * (NT * NV) + r];
    }
    for (int idx = tid; idx < CG * TB; idx += 384)
        xs[idx / TB][idx % TB][NV] = 0.f;

    // ---- stage BnA for this h ----
    {
        const float* src = &g_bna[0][0][0][0];
        float* dst = &bna_s[0][0][0];
        for (int idx = tid; idx < NK * NV * NVP; idx += 384) {
            int k = idx / (NV * NVP), rem = idx % (NV * NVP);
            dst[idx] = src[((size_t)(k * NH + h)) * (NV * NVP) + rem];
        }
    }
    // ---- stage weights for this h ----
    {
        const float* src = &g_ws[0][0][0][0];
        float* dst = &ws_s[0][0][0];
        for (int idx = tid; idx < NK * CG * CG; idx += 384) {
            int k = idx / (CG * CG), rem = idx % (CG * CG);
            dst[idx] = src[((size_t)(k * NH + h)) * (CG * CG) + rem];
        }
    }
    if (tid < CG) bias_s[tid] = g_bias[h * CG + tid];
    __syncthreads();

    if (tid < TB * NV) {
        const int t = tid / NV;
        const int w = tid % NV;

        float acc[CG];
        #pragma unroll
        for (int o = 0; o < CG; o++)
            acc[o] = bias_s[o] + xs[o][t][w];   // bias + residual

        #pragma unroll
        for (int k = 0; k < NK; k++) {
            // load BnA column (for this w) into registers, vectorized
            float bcol[NVP];
            {
                const float4* bp = (const float4*)&bna_s[k][w][0];
                #pragma unroll
                for (int q = 0; q < 6; q++) {
                    float4 f = bp[q];
                    bcol[4*q+0] = f.x; bcol[4*q+1] = f.y;
                    bcol[4*q+2] = f.z; bcol[4*q+3] = f.w;
                }
            }
            // adjacency contraction: tmp[c] = sum_v x[c,t,v] * BnA[v,w]
            float tmp[CG];
            #pragma unroll
            for (int c = 0; c < CG; c++) {
                const float4* xp = (const float4*)&xs[c][t][0];
                float s = 0.f;
                #pragma unroll
                for (int q = 0; q < 6; q++) {
                    float4 f = xp[q];
                    s += f.x * bcol[4*q+0] + f.y * bcol[4*q+1]
                       + f.z * bcol[4*q+2] + f.w * bcol[4*q+3];
                }
                tmp[c] = s;
            }
            // channel mix (BN folded): acc[o] += sum_c tmp[c] * ws[k][o][c]
            #pragma unroll
            for (int o = 0; o < CG; o++) {
                const float4* wp = (const float4*)&ws_s[k][o][0];
                float s = acc[o];
                #pragma unroll
                for (int q = 0; q < 4; q++) {
                    float4 f = wp[q];
                    s += tmp[4*q+0] * f.x + tmp[4*q+1] * f.y
                       + tmp[4*q+2] * f.z + tmp[4*q+3] * f.w;
                }
                acc[o] = s;
            }
        }

        float* obase = out + ((size_t)(n * NC + h * CG)) * (NT * NV)
                           + (size_t)(t0 + t) * NV + w;
        #pragma unroll
        for (int o = 0; o < CG; o++)
            obase[(size_t)o * (NT * NV)] = fmaxf(acc[o], 0.f);
    }
}

extern "C" void kernel_launch(void* const* d_in, const int* in_sizes, int n_in,
                              void* d_out, int out_size)
{
    const float* x      = (const float*)d_in[0];
    const float* emb    = (const float*)d_in[1];
    const float* A      = (const float*)d_in[2];
    const float* conv_w = (const float*)d_in[3];
    const float* conv_b = (const float*)d_in[4];
    const float* gamma  = (const float*)d_in[5];
    const float* beta   = (const float*)d_in[6];
    const float* mean   = (const float*)d_in[7];
    const float* var    = (const float*)d_in[8];
    const int*   hop    = (const int*)d_in[9];

    int n_hop = in_sizes[1] / (NK * NH);

    precompute_kernel<<<NK * NH + 1, 256>>>(emb, A, conv_w, conv_b,
                                            gamma, beta, mean, var, hop, n_hop);

    dim3 grid(NT / TB, NN, NH);
    blockgcn_main_kernel<<<grid, 384>>>(x, (float*)d_out);
}